// round 1
// baseline (speedup 1.0000x reference)
#include <cuda_runtime.h>
#include <cstdint>
#include <cfloat>

// IBQ vector quantization:
//   d[b,n] = (sum(z[b]^2) + sum(e[n]^2)) - 2 * dot(z[b], e[n])   (fp32, matching jnp rounding)
//   idx[b] = argmin_n d[b,n]  (first index wins ties)
//   z_q[b] = e[idx[b]]
//
// Fused GEMM+argmin. z tile resident in SMEM (transposed), e streamed in K-slabs.
// Inner product uses packed fma.rn.f32x2 (full-rate fp32 on Blackwell).

#define DIM     256
#define BM      128
#define BN      128
#define BK      32
#define NSLAB   (DIM / BK)
#define THREADS 256
#define MAX_B   32768
#define MAX_NE  8192

__device__ float g_sz[MAX_B];
__device__ float g_se[MAX_NE];

typedef unsigned long long ull;

#define PACK2(d, x, y) \
    asm("mov.b64 %0, {%1, %2};" : "=l"(d) : "r"(__float_as_uint(x)), "r"(__float_as_uint(y)))
#define FMA2(acc, a, b) \
    asm("fma.rn.f32x2 %0, %1, %2, %3;" : "=l"(acc) : "l"(a), "l"(b), "l"(acc))
#define UNPACK2(x, y, d) \
    asm("mov.b64 {%0, %1}, %2;" : "=r"(x), "=r"(y) : "l"(d))

// One warp per row: fp32 sum of squares over DIM=256.
__global__ void row_sumsq_kernel(const float* __restrict__ x, float* __restrict__ o, int rows) {
    int w = (int)((blockIdx.x * blockDim.x + threadIdx.x) >> 5);
    int lane = threadIdx.x & 31;
    if (w >= rows) return;
    const float4* r = (const float4*)(x + (size_t)w * DIM);
    float4 v0 = r[lane * 2];
    float4 v1 = r[lane * 2 + 1];
    float s = v0.x * v0.x;
    s += v0.y * v0.y; s += v0.z * v0.z; s += v0.w * v0.w;
    s += v1.x * v1.x; s += v1.y * v1.y; s += v1.z * v1.z; s += v1.w * v1.w;
#pragma unroll
    for (int off = 16; off; off >>= 1) s += __shfl_xor_sync(0xffffffffu, s, off);
    if (lane == 0) o[w] = s;
}

__global__ void __launch_bounds__(THREADS, 1)
vq_argmin_kernel(const float* __restrict__ z,
                 const float* __restrict__ emb,
                 const float* __restrict__ sz,
                 const float* __restrict__ se,
                 float* __restrict__ outp,
                 int B, int NE, int mode, long long idx_off)
{
    extern __shared__ float smem[];
    float* sm_z  = smem;                 // [DIM][BM] transposed z tile: 32768 floats
    float* sm_e  = smem + DIM * BM;      // [BK][BN] e slab: 4096 floats
    float* run_d = sm_e + BK * BN;       // [BM]
    int*   run_n = (int*)(run_d + BM);   // [BM]

    const int tid = threadIdx.x;
    const int tx = tid & 15;             // col group (8 cols each)
    const int ty = tid >> 4;             // row group (8 rows each)
    const int bbase = blockIdx.x * BM;

    // ---- load z tile, transposed: z[bbase+r][k] -> sm_z[k*BM + r] ----
    {
        int r = tid >> 1;
        int half = tid & 1;              // which 128-wide k half
        const float4* src = (const float4*)(z + (size_t)(bbase + r) * DIM + half * 128);
#pragma unroll
        for (int q = 0; q < 32; q++) {
            float4 v = src[q];
            int k = half * 128 + q * 4;
            sm_z[(k + 0) * BM + r] = v.x;
            sm_z[(k + 1) * BM + r] = v.y;
            sm_z[(k + 2) * BM + r] = v.z;
            sm_z[(k + 3) * BM + r] = v.w;
        }
    }
    if (tid < BM) { run_d[tid] = FLT_MAX; run_n[tid] = 0; }

    float szr[8];
#pragma unroll
    for (int i = 0; i < 8; i++) szr[i] = sz[bbase + ty * 8 + i];

    __syncthreads();

    const int ec = tid >> 1;             // e column within BN (0..127)
    const int ekh = (tid & 1) * 16;      // local k offset within slab (0 or 16)

    for (int nbase = 0; nbase < NE; nbase += BN) {
        ull acc2[8][4];
#pragma unroll
        for (int i = 0; i < 8; i++)
#pragma unroll
            for (int j = 0; j < 4; j++) acc2[i][j] = 0ull;

        // prefetch slab 0 into registers
        float4 pf0, pf1, pf2, pf3;
        {
            const float4* src = (const float4*)(emb + (size_t)(nbase + ec) * DIM + ekh);
            pf0 = src[0]; pf1 = src[1]; pf2 = src[2]; pf3 = src[3];
        }

#pragma unroll 1
        for (int s = 0; s < NSLAB; s++) {
            __syncthreads();   // previous slab's compute done before overwrite
            {
                float* dst = sm_e + ec;
                dst[(ekh + 0)  * BN] = pf0.x; dst[(ekh + 1)  * BN] = pf0.y;
                dst[(ekh + 2)  * BN] = pf0.z; dst[(ekh + 3)  * BN] = pf0.w;
                dst[(ekh + 4)  * BN] = pf1.x; dst[(ekh + 5)  * BN] = pf1.y;
                dst[(ekh + 6)  * BN] = pf1.z; dst[(ekh + 7)  * BN] = pf1.w;
                dst[(ekh + 8)  * BN] = pf2.x; dst[(ekh + 9)  * BN] = pf2.y;
                dst[(ekh + 10) * BN] = pf2.z; dst[(ekh + 11) * BN] = pf2.w;
                dst[(ekh + 12) * BN] = pf3.x; dst[(ekh + 13) * BN] = pf3.y;
                dst[(ekh + 14) * BN] = pf3.z; dst[(ekh + 15) * BN] = pf3.w;
            }
            __syncthreads();
            if (s + 1 < NSLAB) {  // prefetch next slab (overlaps with compute)
                const float4* src = (const float4*)(emb + (size_t)(nbase + ec) * DIM
                                                    + (s + 1) * BK + ekh);
                pf0 = src[0]; pf1 = src[1]; pf2 = src[2]; pf3 = src[3];
            }
            const float* zs = sm_z + (s * BK) * BM + ty * 8;
            const float* es = sm_e + tx * 8;
#pragma unroll 8
            for (int kk = 0; kk < BK; kk++) {
                float4 a0 = *(const float4*)(zs + kk * BM);
                float4 a1 = *(const float4*)(zs + kk * BM + 4);
                float4 b0 = *(const float4*)(es + kk * BN);
                float4 b1 = *(const float4*)(es + kk * BN + 4);
                ull bb0, bb1, bb2, bb3;
                PACK2(bb0, b0.x, b0.y); PACK2(bb1, b0.z, b0.w);
                PACK2(bb2, b1.x, b1.y); PACK2(bb3, b1.z, b1.w);
                float av[8] = {a0.x, a0.y, a0.z, a0.w, a1.x, a1.y, a1.z, a1.w};
#pragma unroll
                for (int i = 0; i < 8; i++) {
                    ull aa; PACK2(aa, av[i], av[i]);
                    FMA2(acc2[i][0], aa, bb0);
                    FMA2(acc2[i][1], aa, bb1);
                    FMA2(acc2[i][2], aa, bb2);
                    FMA2(acc2[i][3], aa, bb3);
                }
            }
        }

        // ---- epilogue: d = (sz + se) - 2p, per-row argmin over this 128-col chunk ----
        float4 se0 = *(const float4*)(se + nbase + tx * 8);
        float4 se1 = *(const float4*)(se + nbase + tx * 8 + 4);
        float sen[8] = {se0.x, se0.y, se0.z, se0.w, se1.x, se1.y, se1.z, se1.w};
#pragma unroll
        for (int i = 0; i < 8; i++) {
            float bd = FLT_MAX; int bn_ = 0;
#pragma unroll
            for (int j2 = 0; j2 < 4; j2++) {
                unsigned plo_u, phi_u;
                UNPACK2(plo_u, phi_u, acc2[i][j2]);
                float plo = __uint_as_float(plo_u);
                float phi = __uint_as_float(phi_u);
                float d0 = (szr[i] + sen[2 * j2])     - 2.0f * plo;
                float d1 = (szr[i] + sen[2 * j2 + 1]) - 2.0f * phi;
                if (d0 < bd) { bd = d0; bn_ = nbase + tx * 8 + 2 * j2; }
                if (d1 < bd) { bd = d1; bn_ = nbase + tx * 8 + 2 * j2 + 1; }
            }
            // reduce across the 16 tx lanes sharing this row (tie -> smaller index)
#pragma unroll
            for (int off = 8; off; off >>= 1) {
                float od = __shfl_down_sync(0xffffffffu, bd, off, 16);
                int   on = __shfl_down_sync(0xffffffffu, bn_, off, 16);
                if (od < bd || (od == bd && on < bn_)) { bd = od; bn_ = on; }
            }
            if (tx == 0) {
                int r = ty * 8 + i;
                if (bd < run_d[r]) { run_d[r] = bd; run_n[r] = bn_; }  // later chunks have larger n
            }
        }
    }

    __syncthreads();

    // ---- output: z_q gather + indices ----
    {
        int r = tid >> 1, half = tid & 1;
        if (mode & 1) {
            int idx = run_n[r];
            const float4* src = (const float4*)(emb + (size_t)idx * DIM + half * 128);
            float4* dst = (float4*)(outp + (size_t)(bbase + r) * DIM + half * 128);
#pragma unroll
            for (int q = 0; q < 32; q++) dst[q] = src[q];
        }
        if ((mode & 2) && tid < BM) {
            outp[idx_off + bbase + tid] = (float)run_n[tid];
        }
    }
}

extern "C" void kernel_launch(void* const* d_in, const int* in_sizes, int n_in,
                              void* d_out, int out_size) {
    const float* z   = (const float*)d_in[0];
    const float* emb = (const float*)d_in[1];
    float* outp = (float*)d_out;

    int B  = in_sizes[0] / DIM;
    int NE = in_sizes[1] / DIM;

    float *sz_ptr, *se_ptr;
    cudaGetSymbolAddress((void**)&sz_ptr, g_sz);
    cudaGetSymbolAddress((void**)&se_ptr, g_se);

    // row sums of squares (8 warps / 256 threads per block)
    row_sumsq_kernel<<<(B  + 7) / 8, 256>>>(z,   sz_ptr, B);
    row_sumsq_kernel<<<(NE + 7) / 8, 256>>>(emb, se_ptr, NE);

    long long zq_elems = (long long)B * DIM;
    int mode; long long idx_off;
    if ((long long)out_size >= zq_elems + B) { mode = 3; idx_off = zq_elems; }
    else if ((long long)out_size >= zq_elems) { mode = 1; idx_off = 0; }
    else { mode = 2; idx_off = 0; }

    size_t smem_bytes = (size_t)(DIM * BM + BK * BN + BM) * sizeof(float) + BM * sizeof(int);
    cudaFuncSetAttribute(vq_argmin_kernel, cudaFuncAttributeMaxDynamicSharedMemorySize,
                         (int)smem_bytes);

    vq_argmin_kernel<<<B / BM, THREADS, smem_bytes>>>(z, emb, sz_ptr, se_ptr, outp,
                                                      B, NE, mode, idx_off);
}